// round 11
// baseline (speedup 1.0000x reference)
#include <cuda_runtime.h>
#include <cstdint>

// Problem constants (shapes fixed by the dataset)
#define NMAX 50000
#define EMAX 1000000
#define DIN 64
#define H1 64
#define H2 64
#define RNUM 8
#define BNUM 30

// ---------------- device scratch (static: no allocs allowed) ----------------
__device__ float4 g_xr[(size_t)NMAX * 512 / 4];    // [N, R*H1] = [N,512]  ~102MB
__device__ float4 g_agg1[(size_t)NMAX * 64 / 4];   // RGCN aggregation
__device__ float4 g_agg2[(size_t)NMAX * 64 / 4];   // GraphConv aggregation
__device__ float4 g_hs[(size_t)NMAX * 64 / 4];     // h * rsqrt(deg_out)
__device__ int    g_deg_out[NMAX];
__device__ int    g_deg_in[NMAX];
__device__ float  g_wrelT[64 * 512];               // [k][r*64+o]
__device__ int    g_src[EMAX];
__device__ int    g_dst[EMAX];
__device__ int    g_et [EMAX];
__device__ int    g_ei_is64;                       // edge_index dtype flag
__device__ int    g_et_sel;                        // which size-E array is edge_type
__device__ int    g_et_is64;                       // edge_type dtype flag

// ---------------- dtype + identity detection (1 thread, byte-safe) ----------------
__device__ int valid64_probe(const void* p, int cnt, long long hi) {
    const long long* a = (const long long*)p;
    int stride = cnt > 64 ? cnt / 64 : 1;
    for (int i = 0; i < 64; i++) {
        int idx = i * stride;
        if (idx >= cnt) break;
        long long v = a[idx];
        if (v < 0 || v >= hi) return 0;
    }
    return 1;
}
__device__ int valid32_probe(const void* p, int cnt, int hi) {
    const int* a = (const int*)p;
    int stride = cnt > 64 ? cnt / 64 : 1;
    for (int i = 0; i < 64; i++) {
        int idx = i * stride;
        if (idx >= cnt) break;
        int v = a[idx];
        if (v < 0 || v >= hi) return 0;
    }
    return 1;
}
__global__ void detect_kernel(const void* ei, const void* etA, const void* etB,
                              int E, int N) {
    // RULE: valid64 ==> int64 (int32 data read as int64 packs two random words
    // per value and essentially never stays in range; the converse is ambiguous).
    g_ei_is64 = valid64_probe(ei, E, N);

    int A32 = valid32_probe(etA, E, 64);
    int A64 = valid64_probe(etA, E / 2, 64);
    int B32 = valid32_probe(etB, E, 64);
    int B64 = valid64_probe(etB, E / 2, 64);
    // edge_norm floats in [0,1) have int bit patterns ~1e9: never valid.
    int selA = (A32 || A64);
    int selB = (B32 || B64);
    if (selA && !selB)      { g_et_sel = 0; g_et_is64 = A64; }
    else if (selB && !selA) { g_et_sel = 1; g_et_is64 = B64; }
    else                    { g_et_sel = 1; g_et_is64 = B64; }
}

// ---------------- zero scratch ----------------
__global__ void zero_kernel(int n) {
    int i = blockIdx.x * blockDim.x + threadIdx.x;
    float4 z = make_float4(0.f, 0.f, 0.f, 0.f);
    int nf4 = n * 16;  // n*64/4
    if (i < nf4) { g_agg1[i] = z; g_agg2[i] = z; }
    if (i < n)   { g_deg_out[i] = 0; g_deg_in[i] = 0; }
}

// ---------------- convert indices + degree counts (clamped: no traps) ----------------
__global__ void convert_kernel(const void* ei, const void* etA, const void* etB,
                               int E, int N) {
    int e = blockIdx.x * blockDim.x + threadIdx.x;
    if (e >= E) return;
    const void* et = g_et_sel ? etB : etA;
    long long s, d, r;
    if (g_ei_is64) {
        s = ((const long long*)ei)[e];
        d = ((const long long*)ei)[E + e];
    } else {
        s = ((const int*)ei)[e];
        d = ((const int*)ei)[E + e];
    }
    if (g_et_is64) r = ((const long long*)et)[e];
    else           r = ((const int*)et)[e];
    int si = (int)s, di = (int)d, ri = (int)r;
    if (si < 0) si = 0; if (si >= N) si = N - 1;   // degrade to wrong, never trap
    if (di < 0) di = 0; if (di >= N) di = N - 1;
    ri &= 7;
    g_src[e] = si; g_dst[e] = di; g_et[e] = ri;
    atomicAdd(&g_deg_out[si], 1);
    atomicAdd(&g_deg_in[di], 1);
}

// ---------------- Wrel^T = einsum('rb,bio->rio', comp, basis), stored [k][r*64+o] ----------------
__global__ void wrel_kernel(const float* __restrict__ comp,
                            const float* __restrict__ basis) {
    int idx = blockIdx.x * blockDim.x + threadIdx.x;
    if (idx >= 64 * 512) return;
    int k = idx >> 9;          // DIN index
    int rem = idx & 511;
    int r = rem >> 6;
    int o = rem & 63;
    float s = 0.f;
#pragma unroll
    for (int b = 0; b < BNUM; b++)
        s = fmaf(comp[r * BNUM + b], basis[b * (DIN * H1) + k * H1 + o], s);
    g_wrelT[idx] = s;
}

// ---------------- GEMM, K=64 fixed: C[M,N] = op(A[M,64]) @ B[64,N] (+ epilogue) ----------------
template<bool PRE, bool ADD, bool BIAS_, bool POST>
__global__ __launch_bounds__(256) void gemm_k64(
    const float* __restrict__ A, const float* __restrict__ B,
    float* __restrict__ C, int M, int N,
    const float* __restrict__ addend, const float* __restrict__ bias,
    const int* __restrict__ predeg, const int* __restrict__ postdeg)
{
    __shared__ float As[32][132];   // transposed slab [k][m], padded
    __shared__ float Bs[32][64];

    const int tid = threadIdx.x;
    const int row0 = blockIdx.y * 128;
    const int col0 = blockIdx.x * 64;

    float acc[8][4];
#pragma unroll
    for (int r = 0; r < 8; r++)
#pragma unroll
        for (int c = 0; c < 4; c++) acc[r][c] = 0.f;

    const int tm = tid >> 4;
    const int tn = tid & 15;

    for (int ks = 0; ks < 64; ks += 32) {
#pragma unroll
        for (int i = 0; i < 4; i++) {
            int j = tid + i * 256;
            int r = j >> 3;
            int c4 = j & 7;
            int row = row0 + r;
            float4 v = make_float4(0.f, 0.f, 0.f, 0.f);
            if (row < M) {
                v = *(const float4*)(A + (size_t)row * 64 + ks + c4 * 4);
                if (PRE) {
                    float s = rsqrtf(fmaxf((float)predeg[row], 1.0f));
                    v.x *= s; v.y *= s; v.z *= s; v.w *= s;
                }
            }
            As[c4 * 4 + 0][r] = v.x;
            As[c4 * 4 + 1][r] = v.y;
            As[c4 * 4 + 2][r] = v.z;
            As[c4 * 4 + 3][r] = v.w;
        }
#pragma unroll
        for (int i = 0; i < 2; i++) {
            int j = tid + i * 256;
            int r = j >> 4;
            int c4 = j & 15;
            *(float4*)&Bs[r][c4 * 4] =
                *(const float4*)(B + (size_t)(ks + r) * N + col0 + c4 * 4);
        }
        __syncthreads();

#pragma unroll
        for (int k = 0; k < 32; k++) {
            float a[8], b[4];
            *(float4*)&a[0] = *(const float4*)&As[k][tm * 8];
            *(float4*)&a[4] = *(const float4*)&As[k][tm * 8 + 4];
            *(float4*)&b[0] = *(const float4*)&Bs[k][tn * 4];
#pragma unroll
            for (int r = 0; r < 8; r++)
#pragma unroll
                for (int c = 0; c < 4; c++)
                    acc[r][c] = fmaf(a[r], b[c], acc[r][c]);
        }
        __syncthreads();
    }

#pragma unroll
    for (int r = 0; r < 8; r++) {
        int row = row0 + tm * 8 + r;
        if (row >= M) break;
        float ps = 1.f;
        if (POST) ps = rsqrtf(fmaxf((float)postdeg[row], 1.0f));
#pragma unroll
        for (int c = 0; c < 4; c++) {
            int col = col0 + tn * 4 + c;
            float v = acc[r][c];
            if (ADD)   v += addend[(size_t)row * N + col];
            if (BIAS_) v += bias[col];
            if (POST)  v *= ps;
            C[(size_t)row * N + col] = v;
        }
    }
}

// ---------------- scatter 1: agg1[dst] += xr[src, etype]  (scalar atomics) ----------------
__global__ void scatter1_kernel(int E) {
    int i = blockIdx.x * blockDim.x + threadIdx.x;
    if (i >= E * 16) return;
    int e = i >> 4;
    int q = i & 15;
    int s = g_src[e];
    int d = g_dst[e];
    int r = g_et[e];
    float4 v = g_xr[(size_t)s * 128 + r * 16 + q];
    float* p = (float*)g_agg1 + (size_t)d * 64 + q * 4;
    atomicAdd(p + 0, v.x);
    atomicAdd(p + 1, v.y);
    atomicAdd(p + 2, v.z);
    atomicAdd(p + 3, v.w);
}

// ---------------- scatter 2: agg2[dst] += hs[src] ----------------
__global__ void scatter2_kernel(int E) {
    int i = blockIdx.x * blockDim.x + threadIdx.x;
    if (i >= E * 16) return;
    int e = i >> 4;
    int q = i & 15;
    int s = g_src[e];
    int d = g_dst[e];
    float4 v = g_hs[(size_t)s * 16 + q];
    float* p = (float*)g_agg2 + (size_t)d * 64 + q * 4;
    atomicAdd(p + 0, v.x);
    atomicAdd(p + 1, v.y);
    atomicAdd(p + 2, v.z);
    atomicAdd(p + 3, v.w);
}

// ---------------- launch ----------------
extern "C" void kernel_launch(void* const* d_in, const int* in_sizes, int n_in,
                              void* d_out, int out_size) {
    // ---- size-based input discovery (robust to harness input ordering) ----
    const float *X = nullptr, *basis = nullptr, *comp = nullptr;
    const float *loopw = nullptr, *bias1 = nullptr, *w2 = nullptr, *bias2 = nullptr;
    const void  *ei = nullptr, *etA = nullptr, *etB = nullptr;
    int E = EMAX;
    {
        int seen4096 = 0, seen64 = 0;
        long long maxsz = 0;
        for (int i = 0; i < n_in; i++) if (in_sizes[i] > maxsz) maxsz = in_sizes[i];
        for (int i = 0; i < n_in; i++)
            if (in_sizes[i] == maxsz && X == nullptr) X = (const float*)d_in[i];
        long long second = 0;
        for (int i = 0; i < n_in; i++) {
            long long sz = in_sizes[i];
            if (sz < maxsz && sz > second) second = sz;
        }
        E = (int)(second / 2);
        for (int i = 0; i < n_in; i++) {
            long long sz = in_sizes[i];
            const void* p = d_in[i];
            if (sz == maxsz && p == (const void*)X) continue;
            if (sz == second && ei == nullptr) { ei = p; continue; }
            if (sz == (long long)E) {           // edge_norm / edge_type: by content
                if (etA == nullptr) etA = p; else etB = p;
                continue;
            }
            if (sz == 122880) { basis = (const float*)p; continue; }
            if (sz == 240)    { comp  = (const float*)p; continue; }
            if (sz == 4096) {
                if (seen4096 == 0) { loopw = (const float*)p; seen4096 = 1; }
                else               { w2    = (const float*)p; }
                continue;
            }
            if (sz == 64) {   // bias1/bias2 are both zeros -> order irrelevant
                if (seen64 == 0) { bias1 = (const float*)p; seen64 = 1; }
                else             { bias2 = (const float*)p; }
                continue;
            }
        }
    }
    float* out = (float*)d_out;
    const int N = out_size / H2;   // 50000 output rows

    // ---- THE FIX: resolve real device addresses of __device__ scratch ----
    // (Host-side identifiers of __device__ symbols are nvcc's host shadows; on
    //  GB300/ATS they are silently dereferenceable by the GPU -> wrong memory,
    //  not a crash. Must use cudaGetSymbolAddress.)
    void *p_xr_, *p_agg1_, *p_agg2_, *p_hs_, *p_do_, *p_di_, *p_w_;
    cudaGetSymbolAddress(&p_xr_,   g_xr);
    cudaGetSymbolAddress(&p_agg1_, g_agg1);
    cudaGetSymbolAddress(&p_agg2_, g_agg2);
    cudaGetSymbolAddress(&p_hs_,   g_hs);
    cudaGetSymbolAddress(&p_do_,   g_deg_out);
    cudaGetSymbolAddress(&p_di_,   g_deg_in);
    cudaGetSymbolAddress(&p_w_,    g_wrelT);
    float* xr_d    = (float*)p_xr_;
    float* agg1_d  = (float*)p_agg1_;
    float* agg2_d  = (float*)p_agg2_;
    float* hs_d    = (float*)p_hs_;
    int*   degout_d = (int*)p_do_;
    int*   degin_d  = (int*)p_di_;
    float* wrelT_d  = (float*)p_w_;

    detect_kernel<<<1, 1>>>(ei, etA, etB, E, N);

    const int ZB = (N * 16 + 255) / 256;
    zero_kernel<<<ZB, 256>>>(N);

    convert_kernel<<<(E + 255) / 256, 256>>>(ei, etA, etB, E, N);
    wrel_kernel<<<(64 * 512 + 255) / 256, 256>>>(comp, basis);

    const int MY = (N + 127) / 128;

    // xr = X @ WrelT : [N,64] @ [64,512]
    gemm_k64<false, false, false, false><<<dim3(8, MY), 256>>>(
        X, wrelT_d, xr_d, N, 512, nullptr, nullptr, nullptr, nullptr);

    // agg1[dst] += xr[src, etype]
    scatter1_kernel<<<(E * 16 + 255) / 256, 256>>>(E);

    // hs = (agg1 + X @ loopw + bias1) * rsqrt(max(deg_out,1))
    gemm_k64<false, true, true, true><<<dim3(1, MY), 256>>>(
        X, loopw, hs_d, N, 64, agg1_d, bias1, nullptr, degout_d);

    // agg2[dst] += hs[src]
    scatter2_kernel<<<(E * 16 + 255) / 256, 256>>>(E);

    // out = (agg2 * rsqrt(max(deg_in,1))) @ w2 + bias2
    gemm_k64<true, false, true, false><<<dim3(1, MY), 256>>>(
        agg2_d, w2, out, N, 64, nullptr, bias2, degin_d, nullptr);
}

// round 13
// speedup vs baseline: 1.4408x; 1.4408x over previous
#include <cuda_runtime.h>
#include <cstdint>

// Problem constants (shapes fixed by the dataset)
#define NMAX 50000
#define EMAX 1000000
#define DIN 64
#define H1 64
#define H2 64
#define RNUM 8
#define BNUM 30

// ---------------- device scratch (static: no allocs allowed) ----------------
__device__ float4 g_xr[(size_t)NMAX * 512 / 4];    // [N, R*H1] = [N,512]  ~102MB
__device__ float4 g_agg1[(size_t)NMAX * 64 / 4];   // RGCN aggregation
__device__ float4 g_agg2[(size_t)NMAX * 64 / 4];   // GraphConv aggregation
__device__ float4 g_hs[(size_t)NMAX * 64 / 4];     // h * rsqrt(deg_out)
__device__ int    g_deg_out[NMAX];
__device__ int    g_deg_in[NMAX];
__device__ float  g_wrelT[64 * 512];               // [k][r*64+o]
__device__ int    g_src[EMAX];
__device__ int    g_dst[EMAX];
__device__ int    g_et [EMAX];
__device__ int    g_ei_is64;
__device__ int    g_et_sel;
__device__ int    g_et_is64;

// vectorized global reduction (sm_90+): 1 lane-op moves 16B
__device__ __forceinline__ void red_add_v4(float* addr, float4 v) {
    asm volatile("red.global.add.v4.f32 [%0], {%1, %2, %3, %4};"
                 :: "l"(addr), "f"(v.x), "f"(v.y), "f"(v.z), "f"(v.w)
                 : "memory");
}

// ---------------- dtype + identity detection (1 thread, byte-safe) ----------------
__device__ int valid64_probe(const void* p, int cnt, long long hi) {
    const long long* a = (const long long*)p;
    int stride = cnt > 64 ? cnt / 64 : 1;
    for (int i = 0; i < 64; i++) {
        int idx = i * stride;
        if (idx >= cnt) break;
        long long v = a[idx];
        if (v < 0 || v >= hi) return 0;
    }
    return 1;
}
__device__ int valid32_probe(const void* p, int cnt, int hi) {
    const int* a = (const int*)p;
    int stride = cnt > 64 ? cnt / 64 : 1;
    for (int i = 0; i < 64; i++) {
        int idx = i * stride;
        if (idx >= cnt) break;
        int v = a[idx];
        if (v < 0 || v >= hi) return 0;
    }
    return 1;
}
__global__ void detect_kernel(const void* ei, const void* etA, const void* etB,
                              int E, int N) {
    // RULE: valid64 ==> int64 (int32 data read as int64 packs two random words
    // per value and essentially never stays in range; the converse is ambiguous).
    g_ei_is64 = valid64_probe(ei, E, N);

    int A32 = valid32_probe(etA, E, 64);
    int A64 = valid64_probe(etA, E / 2, 64);
    int B32 = valid32_probe(etB, E, 64);
    int B64 = valid64_probe(etB, E / 2, 64);
    int selA = (A32 || A64);
    int selB = (B32 || B64);
    if (selA && !selB)      { g_et_sel = 0; g_et_is64 = A64; }
    else if (selB && !selA) { g_et_sel = 1; g_et_is64 = B64; }
    else                    { g_et_sel = 1; g_et_is64 = B64; }
}

// ---------------- zero scratch ----------------
__global__ void zero_kernel(int n) {
    int i = blockIdx.x * blockDim.x + threadIdx.x;
    float4 z = make_float4(0.f, 0.f, 0.f, 0.f);
    int nf4 = n * 16;
    if (i < nf4) { g_agg1[i] = z; g_agg2[i] = z; }
    if (i < n)   { g_deg_out[i] = 0; g_deg_in[i] = 0; }
}

// ---------------- convert indices + degree counts (clamped: no traps) ----------------
__global__ void convert_kernel(const void* ei, const void* etA, const void* etB,
                               int E, int N) {
    int e = blockIdx.x * blockDim.x + threadIdx.x;
    if (e >= E) return;
    const void* et = g_et_sel ? etB : etA;
    long long s, d, r;
    if (g_ei_is64) {
        s = ((const long long*)ei)[e];
        d = ((const long long*)ei)[E + e];
    } else {
        s = ((const int*)ei)[e];
        d = ((const int*)ei)[E + e];
    }
    if (g_et_is64) r = ((const long long*)et)[e];
    else           r = ((const int*)et)[e];
    int si = (int)s, di = (int)d, ri = (int)r;
    if (si < 0) si = 0; if (si >= N) si = N - 1;
    if (di < 0) di = 0; if (di >= N) di = N - 1;
    ri &= 7;
    g_src[e] = si; g_dst[e] = di; g_et[e] = ri;
    atomicAdd(&g_deg_out[si], 1);
    atomicAdd(&g_deg_in[di], 1);
}

// ---------------- Wrel^T, stored [k][r*64+o] ----------------
__global__ void wrel_kernel(const float* __restrict__ comp,
                            const float* __restrict__ basis) {
    int idx = blockIdx.x * blockDim.x + threadIdx.x;
    if (idx >= 64 * 512) return;
    int k = idx >> 9;
    int rem = idx & 511;
    int r = rem >> 6;
    int o = rem & 63;
    float s = 0.f;
#pragma unroll
    for (int b = 0; b < BNUM; b++)
        s = fmaf(comp[r * BNUM + b], basis[b * (DIN * H1) + k * H1 + o], s);
    g_wrelT[idx] = s;
}

// ---------------- big GEMM (xr): C[M,512] = A[M,64] @ B[64,512] ----------------
// Tile 128x128, 256 threads, 8x8 microtile, K slabs of 32.
__global__ __launch_bounds__(256) void gemm_xr(
    const float* __restrict__ A, const float* __restrict__ B,
    float* __restrict__ C, int M)
{
    __shared__ float As[32][132];   // [k][m], padded
    __shared__ float Bs[32][128];

    const int tid = threadIdx.x;
    const int row0 = blockIdx.y * 128;
    const int col0 = blockIdx.x * 128;

    float acc[8][8];
#pragma unroll
    for (int r = 0; r < 8; r++)
#pragma unroll
        for (int c = 0; c < 8; c++) acc[r][c] = 0.f;

    const int tm = tid >> 4;   // 0..15 -> rows tm*8..+7
    const int tn = tid & 15;   // 0..15 -> cols tn*8..+7

    for (int ks = 0; ks < 64; ks += 32) {
        // A slab: 128 rows x 32 k = 1024 float4, 4/thread (transposed store)
#pragma unroll
        for (int i = 0; i < 4; i++) {
            int j = tid + i * 256;
            int r = j >> 3;          // 0..127
            int c4 = j & 7;          // 0..7 (k/4)
            int row = row0 + r;
            float4 v = make_float4(0.f, 0.f, 0.f, 0.f);
            if (row < M)
                v = *(const float4*)(A + (size_t)row * 64 + ks + c4 * 4);
            As[c4 * 4 + 0][r] = v.x;
            As[c4 * 4 + 1][r] = v.y;
            As[c4 * 4 + 2][r] = v.z;
            As[c4 * 4 + 3][r] = v.w;
        }
        // B slab: 32 k x 128 cols = 1024 float4, 4/thread
#pragma unroll
        for (int i = 0; i < 4; i++) {
            int j = tid + i * 256;
            int r = j >> 5;          // 0..31
            int c4 = j & 31;         // 0..31
            *(float4*)&Bs[r][c4 * 4] =
                *(const float4*)(B + (size_t)(ks + r) * 512 + col0 + c4 * 4);
        }
        __syncthreads();

#pragma unroll
        for (int k = 0; k < 32; k++) {
            float a[8], b[8];
            *(float4*)&a[0] = *(const float4*)&As[k][tm * 8];
            *(float4*)&a[4] = *(const float4*)&As[k][tm * 8 + 4];
            *(float4*)&b[0] = *(const float4*)&Bs[k][tn * 8];
            *(float4*)&b[4] = *(const float4*)&Bs[k][tn * 8 + 4];
#pragma unroll
            for (int r = 0; r < 8; r++)
#pragma unroll
                for (int c = 0; c < 8; c++)
                    acc[r][c] = fmaf(a[r], b[c], acc[r][c]);
        }
        __syncthreads();
    }

#pragma unroll
    for (int r = 0; r < 8; r++) {
        int row = row0 + tm * 8 + r;
        if (row >= M) break;
        float* crow = C + (size_t)row * 512 + col0 + tn * 8;
        *(float4*)(crow)     = *(float4*)&acc[r][0];
        *(float4*)(crow + 4) = *(float4*)&acc[r][4];
    }
}

// ---------------- small GEMM, K=64: C[M,64] = op(A[M,64]) @ B[64,64] + epi ----------------
template<bool PRE, bool ADD, bool BIAS_, bool POST>
__global__ __launch_bounds__(256) void gemm_k64(
    const float* __restrict__ A, const float* __restrict__ B,
    float* __restrict__ C, int M, int N,
    const float* __restrict__ addend, const float* __restrict__ bias,
    const int* __restrict__ predeg, const int* __restrict__ postdeg)
{
    __shared__ float As[32][132];
    __shared__ float Bs[32][64];

    const int tid = threadIdx.x;
    const int row0 = blockIdx.y * 128;
    const int col0 = blockIdx.x * 64;

    float acc[8][4];
#pragma unroll
    for (int r = 0; r < 8; r++)
#pragma unroll
        for (int c = 0; c < 4; c++) acc[r][c] = 0.f;

    const int tm = tid >> 4;
    const int tn = tid & 15;

    for (int ks = 0; ks < 64; ks += 32) {
#pragma unroll
        for (int i = 0; i < 4; i++) {
            int j = tid + i * 256;
            int r = j >> 3;
            int c4 = j & 7;
            int row = row0 + r;
            float4 v = make_float4(0.f, 0.f, 0.f, 0.f);
            if (row < M) {
                v = *(const float4*)(A + (size_t)row * 64 + ks + c4 * 4);
                if (PRE) {
                    float s = rsqrtf(fmaxf((float)predeg[row], 1.0f));
                    v.x *= s; v.y *= s; v.z *= s; v.w *= s;
                }
            }
            As[c4 * 4 + 0][r] = v.x;
            As[c4 * 4 + 1][r] = v.y;
            As[c4 * 4 + 2][r] = v.z;
            As[c4 * 4 + 3][r] = v.w;
        }
#pragma unroll
        for (int i = 0; i < 2; i++) {
            int j = tid + i * 256;
            int r = j >> 4;
            int c4 = j & 15;
            *(float4*)&Bs[r][c4 * 4] =
                *(const float4*)(B + (size_t)(ks + r) * N + col0 + c4 * 4);
        }
        __syncthreads();

#pragma unroll
        for (int k = 0; k < 32; k++) {
            float a[8], b[4];
            *(float4*)&a[0] = *(const float4*)&As[k][tm * 8];
            *(float4*)&a[4] = *(const float4*)&As[k][tm * 8 + 4];
            *(float4*)&b[0] = *(const float4*)&Bs[k][tn * 4];
#pragma unroll
            for (int r = 0; r < 8; r++)
#pragma unroll
                for (int c = 0; c < 4; c++)
                    acc[r][c] = fmaf(a[r], b[c], acc[r][c]);
        }
        __syncthreads();
    }

#pragma unroll
    for (int r = 0; r < 8; r++) {
        int row = row0 + tm * 8 + r;
        if (row >= M) break;
        float ps = 1.f;
        if (POST) ps = rsqrtf(fmaxf((float)postdeg[row], 1.0f));
#pragma unroll
        for (int c = 0; c < 4; c++) {
            int col = col0 + tn * 4 + c;
            float v = acc[r][c];
            if (ADD)   v += addend[(size_t)row * N + col];
            if (BIAS_) v += bias[col];
            if (POST)  v *= ps;
            C[(size_t)row * N + col] = v;
        }
    }
}

// ---------------- scatter 1: agg1[dst] += xr[src, etype]  (v4 red) ----------------
__global__ void scatter1_kernel(int E) {
    int i = blockIdx.x * blockDim.x + threadIdx.x;
    if (i >= E * 16) return;
    int e = i >> 4;
    int q = i & 15;
    int s = g_src[e];
    int d = g_dst[e];
    int r = g_et[e];
    float4 v = g_xr[(size_t)s * 128 + r * 16 + q];
    red_add_v4((float*)g_agg1 + (size_t)d * 64 + q * 4, v);
}

// ---------------- scatter 2: agg2[dst] += hs[src]  (v4 red) ----------------
__global__ void scatter2_kernel(int E) {
    int i = blockIdx.x * blockDim.x + threadIdx.x;
    if (i >= E * 16) return;
    int e = i >> 4;
    int q = i & 15;
    int s = g_src[e];
    int d = g_dst[e];
    float4 v = g_hs[(size_t)s * 16 + q];
    red_add_v4((float*)g_agg2 + (size_t)d * 64 + q * 4, v);
}

// ---------------- launch ----------------
extern "C" void kernel_launch(void* const* d_in, const int* in_sizes, int n_in,
                              void* d_out, int out_size) {
    // ---- size-based input discovery (robust to harness input ordering) ----
    const float *X = nullptr, *basis = nullptr, *comp = nullptr;
    const float *loopw = nullptr, *bias1 = nullptr, *w2 = nullptr, *bias2 = nullptr;
    const void  *ei = nullptr, *etA = nullptr, *etB = nullptr;
    int E = EMAX;
    {
        int seen4096 = 0, seen64 = 0;
        long long maxsz = 0;
        for (int i = 0; i < n_in; i++) if (in_sizes[i] > maxsz) maxsz = in_sizes[i];
        for (int i = 0; i < n_in; i++)
            if (in_sizes[i] == maxsz && X == nullptr) X = (const float*)d_in[i];
        long long second = 0;
        for (int i = 0; i < n_in; i++) {
            long long sz = in_sizes[i];
            if (sz < maxsz && sz > second) second = sz;
        }
        E = (int)(second / 2);
        for (int i = 0; i < n_in; i++) {
            long long sz = in_sizes[i];
            const void* p = d_in[i];
            if (sz == maxsz && p == (const void*)X) continue;
            if (sz == second && ei == nullptr) { ei = p; continue; }
            if (sz == (long long)E) {
                if (etA == nullptr) etA = p; else etB = p;
                continue;
            }
            if (sz == 122880) { basis = (const float*)p; continue; }
            if (sz == 240)    { comp  = (const float*)p; continue; }
            if (sz == 4096) {
                if (seen4096 == 0) { loopw = (const float*)p; seen4096 = 1; }
                else               { w2    = (const float*)p; }
                continue;
            }
            if (sz == 64) {
                if (seen64 == 0) { bias1 = (const float*)p; seen64 = 1; }
                else             { bias2 = (const float*)p; }
                continue;
            }
        }
    }
    float* out = (float*)d_out;
    const int N = out_size / H2;   // 50000 output rows

    // Resolve real device addresses of __device__ scratch (host identifiers
    // are shadow symbols; ATS makes misuse silent on GB300).
    void *p_xr_, *p_agg1_, *p_agg2_, *p_hs_, *p_do_, *p_di_, *p_w_;
    cudaGetSymbolAddress(&p_xr_,   g_xr);
    cudaGetSymbolAddress(&p_agg1_, g_agg1);
    cudaGetSymbolAddress(&p_agg2_, g_agg2);
    cudaGetSymbolAddress(&p_hs_,   g_hs);
    cudaGetSymbolAddress(&p_do_,   g_deg_out);
    cudaGetSymbolAddress(&p_di_,   g_deg_in);
    cudaGetSymbolAddress(&p_w_,    g_wrelT);
    float* xr_d     = (float*)p_xr_;
    float* agg1_d   = (float*)p_agg1_;
    float* agg2_d   = (float*)p_agg2_;
    float* hs_d     = (float*)p_hs_;
    int*   degout_d = (int*)p_do_;
    int*   degin_d  = (int*)p_di_;
    float* wrelT_d  = (float*)p_w_;

    detect_kernel<<<1, 1>>>(ei, etA, etB, E, N);

    const int ZB = (N * 16 + 255) / 256;
    zero_kernel<<<ZB, 256>>>(N);

    convert_kernel<<<(E + 255) / 256, 256>>>(ei, etA, etB, E, N);
    wrel_kernel<<<(64 * 512 + 255) / 256, 256>>>(comp, basis);

    const int MY = (N + 127) / 128;

    // xr = X @ WrelT : [N,64] @ [64,512]  (128x128 tiles, 8x8 microtile)
    gemm_xr<<<dim3(4, MY), 256>>>(X, wrelT_d, xr_d, N);

    // agg1[dst] += xr[src, etype]
    scatter1_kernel<<<(E * 16 + 255) / 256, 256>>>(E);

    // hs = (agg1 + X @ loopw + bias1) * rsqrt(max(deg_out,1))
    gemm_k64<false, true, true, true><<<dim3(1, MY), 256>>>(
        X, loopw, hs_d, N, 64, agg1_d, bias1, nullptr, degout_d);

    // agg2[dst] += hs[src]
    scatter2_kernel<<<(E * 16 + 255) / 256, 256>>>(E);

    // out = (agg2 * rsqrt(max(deg_in,1))) @ w2 + bias2
    gemm_k64<true, false, true, false><<<dim3(1, MY), 256>>>(
        agg2_d, w2, out, N, 64, nullptr, bias2, degin_d, nullptr);
}